// round 4
// baseline (speedup 1.0000x reference)
#include <cuda_runtime.h>
#include <cuda_bf16.h>
#include <math.h>
#include <stdint.h>

#define T_TOKENS 8192
#define H_DIM    2048
#define I_DIM    1408
#define N_EXP    8
#define MAXTOK   8192
#define TOTROWS  (2*T_TOKENS)
#define WELEMS   (N_EXP * I_DIM * H_DIM)   // 23,068,672 (same for all 3 weights)

// ---------------- scratch (static device globals) ----------------
__device__ __nv_bfloat16 g_xn_hi[(size_t)T_TOKENS*H_DIM];
__device__ __nv_bfloat16 g_xn_lo[(size_t)T_TOKENS*H_DIM];
__device__ __nv_bfloat16 g_h_hi[(size_t)(TOTROWS+128)*I_DIM];
__device__ __nv_bfloat16 g_h_lo[(size_t)(TOTROWS+128)*I_DIM];
__device__ float g_y[(size_t)TOTROWS*H_DIM];
__device__ int   g_cnt[N_EXP];
__device__ int   g_off[N_EXP];
__device__ int   g_tok[N_EXP*MAXTOK];
__device__ int   g_te[2*T_TOKENS];
__device__ int   g_tp[2*T_TOKENS];
__device__ float g_tw[2*T_TOKENS];
// pre-split weights (hi/lo bf16)
__device__ __nv_bfloat16 g_wg_hi[(size_t)WELEMS];
__device__ __nv_bfloat16 g_wg_lo[(size_t)WELEMS];
__device__ __nv_bfloat16 g_wu_hi[(size_t)WELEMS];
__device__ __nv_bfloat16 g_wu_lo[(size_t)WELEMS];
__device__ __nv_bfloat16 g_wd_hi[(size_t)WELEMS];
__device__ __nv_bfloat16 g_wd_lo[(size_t)WELEMS];

// ---------------- helpers ----------------
__device__ __forceinline__ uint32_t smem_u32(const void* p) {
    uint32_t a;
    asm("{ .reg .u64 t; cvta.to.shared.u64 t, %1; cvt.u32.u64 %0, t; }" : "=r"(a) : "l"(p));
    return a;
}
__device__ __forceinline__ void ldsm_x4(uint32_t* r, uint32_t addr) {
    asm volatile("ldmatrix.sync.aligned.m8n8.x4.shared.b16 {%0,%1,%2,%3}, [%4];"
        : "=r"(r[0]), "=r"(r[1]), "=r"(r[2]), "=r"(r[3]) : "r"(addr));
}
__device__ __forceinline__ void mma_bf16(float* c, const uint32_t* a, const uint32_t* b) {
    asm volatile(
        "mma.sync.aligned.m16n8k16.row.col.f32.bf16.bf16.f32 "
        "{%0,%1,%2,%3}, {%4,%5,%6,%7}, {%8,%9}, {%0,%1,%2,%3};"
        : "+f"(c[0]), "+f"(c[1]), "+f"(c[2]), "+f"(c[3])
        : "r"(a[0]), "r"(a[1]), "r"(a[2]), "r"(a[3]), "r"(b[0]), "r"(b[1]));
}
__device__ __forceinline__ void cp16(uint32_t dst, const void* src, uint32_t sz) {
    asm volatile("cp.async.cg.shared.global [%0], [%1], 16, %2;"
        :: "r"(dst), "l"(src), "r"(sz) : "memory");
}
#define CP_COMMIT() asm volatile("cp.async.commit_group;" ::: "memory")
template<int N> __device__ __forceinline__ void cp_wait() {
    asm volatile("cp.async.wait_group %0;" :: "n"(N) : "memory");
}
__device__ __forceinline__ void split_bf16(float x, __nv_bfloat16& h, __nv_bfloat16& l) {
    h = __float2bfloat16(x);
    l = __float2bfloat16(x - __bfloat162float(h));
}
__device__ __forceinline__ uint32_t pack2(__nv_bfloat16 a, __nv_bfloat16 b) {
    __nv_bfloat162 v = __halves2bfloat162(a, b);
    return *reinterpret_cast<uint32_t*>(&v);
}

// ---------------------------------------------------------------------------
__global__ void reset_kernel() {
    if (threadIdx.x < N_EXP) g_cnt[threadIdx.x] = 0;
}

// ---------------------------------------------------------------------------
// pre-split weights: fp32 -> (hi, lo) bf16
__global__ __launch_bounds__(256) void split_kernel(
    const float* __restrict__ src, __nv_bfloat16* __restrict__ hi,
    __nv_bfloat16* __restrict__ lo, int n4)
{
    int i = blockIdx.x * 256 + threadIdx.x;
    if (i >= n4) return;
    float4 v = ((const float4*)src)[i];
    __nv_bfloat16 h0,l0,h1,l1,h2,l2,h3,l3;
    split_bf16(v.x,h0,l0); split_bf16(v.y,h1,l1);
    split_bf16(v.z,h2,l2); split_bf16(v.w,h3,l3);
    ((uint2*)hi)[i] = make_uint2(pack2(h0,h1), pack2(h2,h3));
    ((uint2*)lo)[i] = make_uint2(pack2(l0,l1), pack2(l2,l3));
}

// ---------------------------------------------------------------------------
__global__ __launch_bounds__(256) void router_kernel(
    const float* __restrict__ hs,
    const float* __restrict__ rmsw,
    const float* __restrict__ rw,
    float* __restrict__ out_logits)
{
    const int t   = blockIdx.x;
    const int tid = threadIdx.x;
    const float* x = hs + (size_t)t * H_DIM;

    float ss = 0.f;
    for (int i = tid; i < H_DIM; i += 256) { float v = x[i]; ss += v * v; }
    __shared__ float red[256];
    red[tid] = ss; __syncthreads();
    for (int s = 128; s > 0; s >>= 1) {
        if (tid < s) red[tid] += red[tid + s];
        __syncthreads();
    }
    __shared__ float s_scale;
    if (tid == 0) s_scale = rsqrtf(red[0] / (float)H_DIM + 1e-6f);
    __syncthreads();
    const float scale = s_scale;

    float acc[N_EXP];
#pragma unroll
    for (int e = 0; e < N_EXP; e++) acc[e] = 0.f;
    for (int i = tid; i < H_DIM; i += 256) {
        float v = x[i] * scale * rmsw[i];
        __nv_bfloat16 h, l; split_bf16(v, h, l);
        g_xn_hi[(size_t)t * H_DIM + i] = h;
        g_xn_lo[(size_t)t * H_DIM + i] = l;
#pragma unroll
        for (int e = 0; e < N_EXP; e++) acc[e] += v * rw[e * H_DIM + i];
    }

    __shared__ float slog[N_EXP];
    for (int e = 0; e < N_EXP; e++) {
        __syncthreads();
        red[tid] = acc[e]; __syncthreads();
        for (int s = 128; s > 0; s >>= 1) {
            if (tid < s) red[tid] += red[tid + s];
            __syncthreads();
        }
        if (tid == 0) slog[e] = red[0];
    }
    __syncthreads();

    if (tid == 0) {
        float l[N_EXP], m = -1e30f;
#pragma unroll
        for (int e = 0; e < N_EXP; e++) {
            l[e] = slog[e];
            out_logits[(size_t)t * N_EXP + e] = l[e];
            m = fmaxf(m, l[e]);
        }
        float p[N_EXP], s = 0.f;
#pragma unroll
        for (int e = 0; e < N_EXP; e++) { p[e] = expf(l[e] - m); s += p[e]; }
#pragma unroll
        for (int e = 0; e < N_EXP; e++) p[e] /= s;

        int a = 0;
#pragma unroll
        for (int e = 1; e < N_EXP; e++) if (p[e] > p[a]) a = e;
        int b = (a == 0) ? 1 : 0;
#pragma unroll
        for (int e = 0; e < N_EXP; e++) if (e != a && p[e] > p[b]) b = e;

        float wsum = p[a] + p[b] + 1e-20f;
        float wa = p[a] / wsum, wb = p[b] / wsum;

        int pa = atomicAdd(&g_cnt[a], 1);
        g_tok[a * MAXTOK + pa] = t;
        g_te[2*t] = a; g_tp[2*t] = pa; g_tw[2*t] = wa;
        int pb = atomicAdd(&g_cnt[b], 1);
        g_tok[b * MAXTOK + pb] = t;
        g_te[2*t+1] = b; g_tp[2*t+1] = pb; g_tw[2*t+1] = wb;
    }
}

// ---------------------------------------------------------------------------
__global__ void offsets_kernel() {
    int run = 0;
    for (int e = 0; e < N_EXP; e++) { g_off[e] = run; run += g_cnt[e]; }
}

// ---------------------------------------------------------------------------
// Double-buffered bf16x3 HMMA GEMMs. Block tile 128(M) x 64(N), K-tile 32.
// smem row pad: 40 bf16 (80B) -> ldmatrix conflict-free, 16B-aligned cp.async.
#define AS 40
#define G1_STAGE 20480                 // bf16 elems per stage
#define G1_SMEM  (2*G1_STAGE*2)        // 81920 B
#define G2_STAGE 15360
#define G2_SMEM  (2*G2_STAGE*2)        // 61440 B

__global__ __launch_bounds__(256, 2) void gemm1_kernel()
{
    const int e  = blockIdx.z;
    const int mt = blockIdx.y;
    const int nt = blockIdx.x;
    const int cnt = g_cnt[e];
    if (mt * 128 >= cnt) return;
    const int tid = threadIdx.x;
    const int wid = tid >> 5;
    const int lane = tid & 31;

    extern __shared__ __nv_bfloat16 sm[];
    __shared__ int stok[128];

    if (tid < 128) {
        int row = mt * 128 + tid;
        stok[tid] = (row < cnt) ? g_tok[e * MAXTOK + row] : -1;
    }
    __syncthreads();

    const __nv_bfloat16* wgh = g_wg_hi + (size_t)e * I_DIM * H_DIM + (size_t)(nt*64) * H_DIM;
    const __nv_bfloat16* wgl = g_wg_lo + (size_t)e * I_DIM * H_DIM + (size_t)(nt*64) * H_DIM;
    const __nv_bfloat16* wuh = g_wu_hi + (size_t)e * I_DIM * H_DIM + (size_t)(nt*64) * H_DIM;
    const __nv_bfloat16* wul = g_wu_lo + (size_t)e * I_DIM * H_DIM + (size_t)(nt*64) * H_DIM;

    // per-thread load coordinates
    const int ar = tid >> 2;               // A row (first half), +64 for second
    const int ac = (tid & 3) * 8;          // A col (bf16)
    const int bn = tid >> 2;               // B row 0..63
    const int bc = (tid & 3) * 8;

    const int tok0 = stok[ar];
    const int tok1 = stok[ar + 64];

#define G1_LOAD(S, KK) do {                                                     \
    __nv_bfloat16* Ah = sm + (S)*G1_STAGE;                                      \
    __nv_bfloat16* Al = Ah + 5120;                                              \
    __nv_bfloat16* Bgh = Ah + 10240; __nv_bfloat16* Bgl = Ah + 12800;           \
    __nv_bfloat16* Buh = Ah + 15360; __nv_bfloat16* Bul = Ah + 17920;           \
    uint32_t v0 = tok0 >= 0 ? 16u : 0u, v1 = tok1 >= 0 ? 16u : 0u;              \
    size_t s0 = (size_t)(tok0 < 0 ? 0 : tok0) * H_DIM + (KK) + ac;              \
    size_t s1 = (size_t)(tok1 < 0 ? 0 : tok1) * H_DIM + (KK) + ac;              \
    cp16(smem_u32(Ah + ar*AS + ac),        g_xn_hi + s0, v0);                   \
    cp16(smem_u32(Al + ar*AS + ac),        g_xn_lo + s0, v0);                   \
    cp16(smem_u32(Ah + (ar+64)*AS + ac),   g_xn_hi + s1, v1);                   \
    cp16(smem_u32(Al + (ar+64)*AS + ac),   g_xn_lo + s1, v1);                   \
    size_t bo = (size_t)bn * H_DIM + (KK) + bc;                                 \
    cp16(smem_u32(Bgh + bn*AS + bc), wgh + bo, 16u);                            \
    cp16(smem_u32(Bgl + bn*AS + bc), wgl + bo, 16u);                            \
    cp16(smem_u32(Buh + bn*AS + bc), wuh + bo, 16u);                            \
    cp16(smem_u32(Bul + bn*AS + bc), wul + bo, 16u);                            \
} while (0)

    float cg[2][4][4], cu[2][4][4];
#pragma unroll
    for (int i = 0; i < 2; i++)
#pragma unroll
        for (int j = 0; j < 4; j++)
#pragma unroll
            for (int k = 0; k < 4; k++) { cg[i][j][k] = 0.f; cu[i][j][k] = 0.f; }

    const int wm = wid >> 1;
    const int wn = wid & 1;
    const int lr = lane & 15;
    const int lc = (lane >> 4) * 8;

    G1_LOAD(0, 0);
    CP_COMMIT();

    const int KT = H_DIM / 32;
    for (int kt = 0; kt < KT; kt++) {
        const int s = kt & 1;
        if (kt + 1 < KT) {
            G1_LOAD(s ^ 1, (kt + 1) * 32);
            CP_COMMIT();
            cp_wait<1>();
        } else {
            cp_wait<0>();
        }
        __syncthreads();

        const __nv_bfloat16* Ah = sm + s*G1_STAGE;
        const __nv_bfloat16* Al = Ah + 5120;
        const __nv_bfloat16* Bgh = Ah + 10240; const __nv_bfloat16* Bgl = Ah + 12800;
        const __nv_bfloat16* Buh = Ah + 15360; const __nv_bfloat16* Bul = Ah + 17920;

#pragma unroll
        for (int ks = 0; ks < 2; ks++) {
            uint32_t ah[2][4], al[2][4];
#pragma unroll
            for (int mf = 0; mf < 2; mf++) {
                int so = (wm*32 + mf*16 + lr) * AS + ks*16 + lc;
                ldsm_x4(ah[mf], smem_u32(Ah + so));
                ldsm_x4(al[mf], smem_u32(Al + so));
            }
            uint32_t bgh[2][4], bgl[2][4], buh[2][4], bul[2][4];
#pragma unroll
            for (int n2 = 0; n2 < 2; n2++) {
                int so = (wn*32 + n2*16 + lr) * AS + ks*16 + lc;
                ldsm_x4(bgh[n2], smem_u32(Bgh + so));
                ldsm_x4(bgl[n2], smem_u32(Bgl + so));
                ldsm_x4(buh[n2], smem_u32(Buh + so));
                ldsm_x4(bul[n2], smem_u32(Bul + so));
            }
#pragma unroll
            for (int mf = 0; mf < 2; mf++)
#pragma unroll
            for (int nf = 0; nf < 4; nf++) {
                int n2 = nf >> 1, nh = nf & 1;
                uint32_t bG [2] = { bgh[n2][nh], bgh[n2][nh+2] };
                uint32_t bGl[2] = { bgl[n2][nh], bgl[n2][nh+2] };
                mma_bf16(cg[mf][nf], ah[mf], bG);
                mma_bf16(cg[mf][nf], al[mf], bG);
                mma_bf16(cg[mf][nf], ah[mf], bGl);
                uint32_t bU [2] = { buh[n2][nh], buh[n2][nh+2] };
                uint32_t bUl[2] = { bul[n2][nh], bul[n2][nh+2] };
                mma_bf16(cu[mf][nf], ah[mf], bU);
                mma_bf16(cu[mf][nf], al[mf], bU);
                mma_bf16(cu[mf][nf], ah[mf], bUl);
            }
        }
        __syncthreads();
    }
#undef G1_LOAD

    // epilogue: h = silu(g) * u, split-bf16 packed stores
    const int off = g_off[e];
#pragma unroll
    for (int mf = 0; mf < 2; mf++)
#pragma unroll
    for (int nf = 0; nf < 4; nf++) {
        int col = nt*64 + wn*32 + nf*8 + (lane & 3)*2;
#pragma unroll
        for (int half = 0; half < 2; half++) {
            int row = mt*128 + wm*32 + mf*16 + (lane >> 2) + half*8;
            if (row < cnt) {
                float g0 = cg[mf][nf][half*2],   g1 = cg[mf][nf][half*2+1];
                float u0 = cu[mf][nf][half*2],   u1 = cu[mf][nf][half*2+1];
                float h0 = (g0 / (1.f + expf(-g0))) * u0;
                float h1 = (g1 / (1.f + expf(-g1))) * u1;
                __nv_bfloat16 a0,b0,a1,b1;
                split_bf16(h0, a0, b0); split_bf16(h1, a1, b1);
                size_t base = (size_t)(off + row) * I_DIM + col;
                *(uint32_t*)(g_h_hi + base) = pack2(a0, a1);
                *(uint32_t*)(g_h_lo + base) = pack2(b0, b1);
            }
        }
    }
}

// ---------------------------------------------------------------------------
__global__ __launch_bounds__(256, 2) void gemm2_kernel()
{
    const int e  = blockIdx.z;
    const int mt = blockIdx.y;
    const int nt = blockIdx.x;
    const int cnt = g_cnt[e];
    if (mt * 128 >= cnt) return;
    const int tid = threadIdx.x;
    const int wid = tid >> 5;
    const int lane = tid & 31;
    const int off = g_off[e];

    extern __shared__ __nv_bfloat16 sm[];

    const __nv_bfloat16* wdh = g_wd_hi + (size_t)e * H_DIM * I_DIM + (size_t)(nt*64) * I_DIM;
    const __nv_bfloat16* wdl = g_wd_lo + (size_t)e * H_DIM * I_DIM + (size_t)(nt*64) * I_DIM;

    const int ar = tid >> 2;
    const int ac = (tid & 3) * 8;
    const int bn = tid >> 2;
    const int bc = (tid & 3) * 8;
    const size_t arow0 = (size_t)(off + mt*128 + ar) * I_DIM;
    const size_t arow1 = (size_t)(off + mt*128 + ar + 64) * I_DIM;

#define G2_LOAD(S, KK) do {                                                     \
    __nv_bfloat16* Ah = sm + (S)*G2_STAGE;                                      \
    __nv_bfloat16* Al = Ah + 5120;                                              \
    __nv_bfloat16* Bh = Ah + 10240; __nv_bfloat16* Bl = Ah + 12800;             \
    cp16(smem_u32(Ah + ar*AS + ac),      g_h_hi + arow0 + (KK) + ac, 16u);      \
    cp16(smem_u32(Al + ar*AS + ac),      g_h_lo + arow0 + (KK) + ac, 16u);      \
    cp16(smem_u32(Ah + (ar+64)*AS + ac), g_h_hi + arow1 + (KK) + ac, 16u);      \
    cp16(smem_u32(Al + (ar+64)*AS + ac), g_h_lo + arow1 + (KK) + ac, 16u);      \
    size_t bo = (size_t)bn * I_DIM + (KK) + bc;                                 \
    cp16(smem_u32(Bh + bn*AS + bc), wdh + bo, 16u);                             \
    cp16(smem_u32(Bl + bn*AS + bc), wdl + bo, 16u);                             \
} while (0)

    float cc[2][4][4];
#pragma unroll
    for (int i = 0; i < 2; i++)
#pragma unroll
        for (int j = 0; j < 4; j++)
#pragma unroll
            for (int k = 0; k < 4; k++) cc[i][j][k] = 0.f;

    const int wm = wid >> 1;
    const int wn = wid & 1;
    const int lr = lane & 15;
    const int lc = (lane >> 4) * 8;

    G2_LOAD(0, 0);
    CP_COMMIT();

    const int KT = I_DIM / 32;
    for (int kt = 0; kt < KT; kt++) {
        const int s = kt & 1;
        if (kt + 1 < KT) {
            G2_LOAD(s ^ 1, (kt + 1) * 32);
            CP_COMMIT();
            cp_wait<1>();
        } else {
            cp_wait<0>();
        }
        __syncthreads();

        const __nv_bfloat16* Ah = sm + s*G2_STAGE;
        const __nv_bfloat16* Al = Ah + 5120;
        const __nv_bfloat16* Bh = Ah + 10240; const __nv_bfloat16* Bl = Ah + 12800;

#pragma unroll
        for (int ks = 0; ks < 2; ks++) {
            uint32_t ah[2][4], al[2][4];
#pragma unroll
            for (int mf = 0; mf < 2; mf++) {
                int so = (wm*32 + mf*16 + lr) * AS + ks*16 + lc;
                ldsm_x4(ah[mf], smem_u32(Ah + so));
                ldsm_x4(al[mf], smem_u32(Al + so));
            }
            uint32_t bh[2][4], bl[2][4];
#pragma unroll
            for (int n2 = 0; n2 < 2; n2++) {
                int so = (wn*32 + n2*16 + lr) * AS + ks*16 + lc;
                ldsm_x4(bh[n2], smem_u32(Bh + so));
                ldsm_x4(bl[n2], smem_u32(Bl + so));
            }
#pragma unroll
            for (int mf = 0; mf < 2; mf++)
#pragma unroll
            for (int nf = 0; nf < 4; nf++) {
                int n2 = nf >> 1, nh = nf & 1;
                uint32_t bH[2] = { bh[n2][nh], bh[n2][nh+2] };
                uint32_t bL[2] = { bl[n2][nh], bl[n2][nh+2] };
                mma_bf16(cc[mf][nf], ah[mf], bH);
                mma_bf16(cc[mf][nf], al[mf], bH);
                mma_bf16(cc[mf][nf], ah[mf], bL);
            }
        }
        __syncthreads();
    }
#undef G2_LOAD

#pragma unroll
    for (int mf = 0; mf < 2; mf++)
#pragma unroll
    for (int nf = 0; nf < 4; nf++) {
        int col = nt*64 + wn*32 + nf*8 + (lane & 3)*2;
#pragma unroll
        for (int half = 0; half < 2; half++) {
            int row = mt*128 + wm*32 + mf*16 + (lane >> 2) + half*8;
            if (row < cnt) {
                float2 v = make_float2(cc[mf][nf][half*2], cc[mf][nf][half*2+1]);
                *(float2*)(g_y + (size_t)(off + row) * H_DIM + col) = v;
            }
        }
    }
}

// ---------------------------------------------------------------------------
__global__ __launch_bounds__(256) void combine_kernel(float* __restrict__ out)
{
    const int t = blockIdx.x;
    const int tid = threadIdx.x;
    const int e0 = g_te[2*t],   p0 = g_tp[2*t];
    const int e1 = g_te[2*t+1], p1 = g_tp[2*t+1];
    const float w0 = g_tw[2*t], w1 = g_tw[2*t+1];
    const float* y0 = g_y + (size_t)(g_off[e0] + p0) * H_DIM;
    const float* y1 = g_y + (size_t)(g_off[e1] + p1) * H_DIM;
    float* o = out + (size_t)t * H_DIM;
#pragma unroll
    for (int it = 0; it < 2; it++) {
        int i = (tid + it * 256) * 4;
        float4 a = *(const float4*)(y0 + i);
        float4 b = *(const float4*)(y1 + i);
        float4 r;
        r.x = w0 * a.x + w1 * b.x;
        r.y = w0 * a.y + w1 * b.y;
        r.z = w0 * a.z + w1 * b.z;
        r.w = w0 * a.w + w1 * b.w;
        *(float4*)(o + i) = r;
    }
}

// ---------------------------------------------------------------------------
extern "C" void kernel_launch(void* const* d_in, const int* in_sizes, int n_in,
                              void* d_out, int out_size)
{
    const float* hs   = (const float*)d_in[0];
    const float* rmsw = (const float*)d_in[1];
    const float* rw   = (const float*)d_in[2];
    const float* wg   = (const float*)d_in[3];
    const float* wu   = (const float*)d_in[4];
    const float* wd   = (const float*)d_in[5];

    float* out        = (float*)d_out;
    float* out_logits = (float*)d_out + (size_t)T_TOKENS * H_DIM;

    cudaFuncSetAttribute(gemm1_kernel, cudaFuncAttributeMaxDynamicSharedMemorySize, G1_SMEM);
    cudaFuncSetAttribute(gemm2_kernel, cudaFuncAttributeMaxDynamicSharedMemorySize, G2_SMEM);

    // pre-split weights
    {
        __nv_bfloat16 *wgh, *wgl, *wuh, *wul, *wdh, *wdl;
        cudaGetSymbolAddress((void**)&wgh, g_wg_hi);
        cudaGetSymbolAddress((void**)&wgl, g_wg_lo);
        cudaGetSymbolAddress((void**)&wuh, g_wu_hi);
        cudaGetSymbolAddress((void**)&wul, g_wu_lo);
        cudaGetSymbolAddress((void**)&wdh, g_wd_hi);
        cudaGetSymbolAddress((void**)&wdl, g_wd_lo);
        int n4 = WELEMS / 4;
        int blocks = (n4 + 255) / 256;
        split_kernel<<<blocks, 256>>>(wg, wgh, wgl, n4);
        split_kernel<<<blocks, 256>>>(wu, wuh, wul, n4);
        split_kernel<<<blocks, 256>>>(wd, wdh, wdl, n4);
    }

    reset_kernel<<<1, 32>>>();
    router_kernel<<<T_TOKENS, 256>>>(hs, rmsw, rw, out_logits);
    offsets_kernel<<<1, 1>>>();

    dim3 g1(I_DIM / 64, T_TOKENS / 128, N_EXP);   // 22 x 64 x 8
    gemm1_kernel<<<g1, 256, G1_SMEM>>>();

    dim3 g2(H_DIM / 64, T_TOKENS / 128, N_EXP);   // 32 x 64 x 8
    gemm2_kernel<<<g2, 256, G2_SMEM>>>();

    combine_kernel<<<T_TOKENS, 256>>>(out);
}

// round 5
// speedup vs baseline: 1.1199x; 1.1199x over previous
#include <cuda_runtime.h>
#include <cuda_bf16.h>
#include <math.h>
#include <stdint.h>

#define T_TOKENS 8192
#define H_DIM    2048
#define I_DIM    1408
#define N_EXP    8
#define MAXTOK   8192
#define TOTROWS  (2*T_TOKENS)
#define WELEMS   (N_EXP * I_DIM * H_DIM)

// ---------------- scratch (static device globals) ----------------
__device__ __nv_bfloat16 g_xn_hi[(size_t)T_TOKENS*H_DIM];
__device__ __nv_bfloat16 g_xn_lo[(size_t)T_TOKENS*H_DIM];
__device__ __nv_bfloat16 g_h_hi[(size_t)(TOTROWS+128)*I_DIM];
__device__ __nv_bfloat16 g_h_lo[(size_t)(TOTROWS+128)*I_DIM];
__device__ float g_y[(size_t)TOTROWS*H_DIM];
__device__ int   g_cnt[N_EXP];
__device__ int   g_off[N_EXP];
__device__ int   g_tok[N_EXP*MAXTOK];
__device__ int   g_te[2*T_TOKENS];
__device__ int   g_tp[2*T_TOKENS];
__device__ float g_tw[2*T_TOKENS];
// pre-split weights (hi/lo bf16)
__device__ __nv_bfloat16 g_wg_hi[(size_t)WELEMS];
__device__ __nv_bfloat16 g_wg_lo[(size_t)WELEMS];
__device__ __nv_bfloat16 g_wu_hi[(size_t)WELEMS];
__device__ __nv_bfloat16 g_wu_lo[(size_t)WELEMS];
__device__ __nv_bfloat16 g_wd_hi[(size_t)WELEMS];
__device__ __nv_bfloat16 g_wd_lo[(size_t)WELEMS];

// ---------------- helpers ----------------
__device__ __forceinline__ uint32_t smem_u32(const void* p) {
    uint32_t a;
    asm("{ .reg .u64 t; cvta.to.shared.u64 t, %1; cvt.u32.u64 %0, t; }" : "=r"(a) : "l"(p));
    return a;
}
__device__ __forceinline__ void ldsm_x4(uint32_t* r, uint32_t addr) {
    asm volatile("ldmatrix.sync.aligned.m8n8.x4.shared.b16 {%0,%1,%2,%3}, [%4];"
        : "=r"(r[0]), "=r"(r[1]), "=r"(r[2]), "=r"(r[3]) : "r"(addr));
}
__device__ __forceinline__ void mma_bf16(float* c, const uint32_t* a, const uint32_t* b) {
    asm volatile(
        "mma.sync.aligned.m16n8k16.row.col.f32.bf16.bf16.f32 "
        "{%0,%1,%2,%3}, {%4,%5,%6,%7}, {%8,%9}, {%0,%1,%2,%3};"
        : "+f"(c[0]), "+f"(c[1]), "+f"(c[2]), "+f"(c[3])
        : "r"(a[0]), "r"(a[1]), "r"(a[2]), "r"(a[3]), "r"(b[0]), "r"(b[1]));
}
__device__ __forceinline__ void split_bf16(float x, __nv_bfloat16& h, __nv_bfloat16& l) {
    h = __float2bfloat16(x);
    l = __float2bfloat16(x - __bfloat162float(h));
}
__device__ __forceinline__ uint32_t pack2(__nv_bfloat16 a, __nv_bfloat16 b) {
    __nv_bfloat162 v = __halves2bfloat162(a, b);
    return *reinterpret_cast<uint32_t*>(&v);
}

// ---------------------------------------------------------------------------
__global__ void reset_kernel() {
    if (threadIdx.x < N_EXP) g_cnt[threadIdx.x] = 0;
}

// ---------------------------------------------------------------------------
// pre-split weights: fp32 -> (hi, lo) bf16
__global__ __launch_bounds__(256) void split_kernel(
    const float* __restrict__ src, __nv_bfloat16* __restrict__ hi,
    __nv_bfloat16* __restrict__ lo, int n4)
{
    int i = blockIdx.x * 256 + threadIdx.x;
    if (i >= n4) return;
    float4 v = ((const float4*)src)[i];
    __nv_bfloat16 h0,l0,h1,l1,h2,l2,h3,l3;
    split_bf16(v.x,h0,l0); split_bf16(v.y,h1,l1);
    split_bf16(v.z,h2,l2); split_bf16(v.w,h3,l3);
    ((uint2*)hi)[i] = make_uint2(pack2(h0,h1), pack2(h2,h3));
    ((uint2*)lo)[i] = make_uint2(pack2(l0,l1), pack2(l2,l3));
}

// ---------------------------------------------------------------------------
__global__ __launch_bounds__(256) void router_kernel(
    const float* __restrict__ hs,
    const float* __restrict__ rmsw,
    const float* __restrict__ rw,
    float* __restrict__ out_logits)
{
    const int t   = blockIdx.x;
    const int tid = threadIdx.x;
    const float* x = hs + (size_t)t * H_DIM;

    float ss = 0.f;
    for (int i = tid; i < H_DIM; i += 256) { float v = x[i]; ss += v * v; }
    __shared__ float red[256];
    red[tid] = ss; __syncthreads();
    for (int s = 128; s > 0; s >>= 1) {
        if (tid < s) red[tid] += red[tid + s];
        __syncthreads();
    }
    __shared__ float s_scale;
    if (tid == 0) s_scale = rsqrtf(red[0] / (float)H_DIM + 1e-6f);
    __syncthreads();
    const float scale = s_scale;

    float acc[N_EXP];
#pragma unroll
    for (int e = 0; e < N_EXP; e++) acc[e] = 0.f;
    for (int i = tid; i < H_DIM; i += 256) {
        float v = x[i] * scale * rmsw[i];
        __nv_bfloat16 h, l; split_bf16(v, h, l);
        g_xn_hi[(size_t)t * H_DIM + i] = h;
        g_xn_lo[(size_t)t * H_DIM + i] = l;
#pragma unroll
        for (int e = 0; e < N_EXP; e++) acc[e] += v * rw[e * H_DIM + i];
    }

    __shared__ float slog[N_EXP];
    for (int e = 0; e < N_EXP; e++) {
        __syncthreads();
        red[tid] = acc[e]; __syncthreads();
        for (int s = 128; s > 0; s >>= 1) {
            if (tid < s) red[tid] += red[tid + s];
            __syncthreads();
        }
        if (tid == 0) slog[e] = red[0];
    }
    __syncthreads();

    if (tid == 0) {
        float l[N_EXP], m = -1e30f;
#pragma unroll
        for (int e = 0; e < N_EXP; e++) {
            l[e] = slog[e];
            out_logits[(size_t)t * N_EXP + e] = l[e];
            m = fmaxf(m, l[e]);
        }
        float p[N_EXP], s = 0.f;
#pragma unroll
        for (int e = 0; e < N_EXP; e++) { p[e] = expf(l[e] - m); s += p[e]; }
#pragma unroll
        for (int e = 0; e < N_EXP; e++) p[e] /= s;

        int a = 0;
#pragma unroll
        for (int e = 1; e < N_EXP; e++) if (p[e] > p[a]) a = e;
        int b = (a == 0) ? 1 : 0;
#pragma unroll
        for (int e = 0; e < N_EXP; e++) if (e != a && p[e] > p[b]) b = e;

        float wsum = p[a] + p[b] + 1e-20f;
        float wa = p[a] / wsum, wb = p[b] / wsum;

        int pa = atomicAdd(&g_cnt[a], 1);
        g_tok[a * MAXTOK + pa] = t;
        g_te[2*t] = a; g_tp[2*t] = pa; g_tw[2*t] = wa;
        int pb = atomicAdd(&g_cnt[b], 1);
        g_tok[b * MAXTOK + pb] = t;
        g_te[2*t+1] = b; g_tp[2*t+1] = pb; g_tw[2*t+1] = wb;
    }
}

// ---------------------------------------------------------------------------
__global__ void offsets_kernel() {
    int run = 0;
    for (int e = 0; e < N_EXP; e++) { g_off[e] = run; run += g_cnt[e]; }
}

// ---------------------------------------------------------------------------
// Tiled bf16x3 HMMA GEMMs (round-3 structure). Block tile 128(M) x 64(N), K-tile 64.
// smem rows padded to 72 bf16 (144B): conflict-free ldmatrix, 16B aligned.
#define AS 72
#define G1_SMEM ((2*128*AS + 4*64*AS) * 2)   // 73728 B
#define G2_SMEM ((2*128*AS + 2*64*AS) * 2)   // 55296 B

__global__ __launch_bounds__(256) void gemm1_kernel()
{
    const int e  = blockIdx.z;
    const int mt = blockIdx.y;
    const int nt = blockIdx.x;
    const int cnt = g_cnt[e];
    if (mt * 128 >= cnt) return;
    const int tid = threadIdx.x;
    const int wid = tid >> 5;
    const int lane = tid & 31;

    extern __shared__ __nv_bfloat16 sm[];
    __shared__ int stok[128];
    __nv_bfloat16* Ah  = sm;
    __nv_bfloat16* Al  = sm + 128*AS;
    __nv_bfloat16* Bgh = sm + 2*128*AS;
    __nv_bfloat16* Bgl = Bgh + 64*AS;
    __nv_bfloat16* Buh = Bgl + 64*AS;
    __nv_bfloat16* Bul = Buh + 64*AS;

    if (tid < 128) {
        int row = mt * 128 + tid;
        stok[tid] = (row < cnt) ? g_tok[e * MAXTOK + row] : -1;
    }

    const size_t wbase = (size_t)e * I_DIM * H_DIM + (size_t)(nt * 64) * H_DIM;
    const __nv_bfloat16* wgh = g_wg_hi + wbase;
    const __nv_bfloat16* wgl = g_wg_lo + wbase;
    const __nv_bfloat16* wuh = g_wu_hi + wbase;
    const __nv_bfloat16* wul = g_wu_lo + wbase;

    float cg[2][4][4], cu[2][4][4];
#pragma unroll
    for (int i = 0; i < 2; i++)
#pragma unroll
        for (int j = 0; j < 4; j++)
#pragma unroll
            for (int k = 0; k < 4; k++) { cg[i][j][k] = 0.f; cu[i][j][k] = 0.f; }

    const int wm = wid >> 1;          // 0..3
    const int wn = wid & 1;           // 0..1
    const int lr = lane & 15;
    const int lc = (lane >> 4) * 8;

    for (int kk = 0; kk < H_DIM; kk += 64) {
        __syncthreads();
        // A: 128 rows x 64 bf16 (hi & lo), gathered by token
#pragma unroll
        for (int p = 0; p < 4; p++) {
            int q = tid + p * 256;
            int r = q >> 3, c8 = (q & 7) * 8;
            int tok = stok[r];
            uint4 vh = make_uint4(0,0,0,0), vl = make_uint4(0,0,0,0);
            if (tok >= 0) {
                size_t gi = (size_t)tok * H_DIM + kk + c8;
                vh = *(const uint4*)(g_xn_hi + gi);
                vl = *(const uint4*)(g_xn_lo + gi);
            }
            int so = r * AS + c8;
            *(uint4*)(Ah + so) = vh;
            *(uint4*)(Al + so) = vl;
        }
        // B: 64 rows x 64 bf16 per array, straight copies of pre-split weights
#pragma unroll
        for (int p = 0; p < 2; p++) {
            int q = tid + p * 256;
            int n = q >> 3, c8 = (q & 7) * 8;
            size_t gi = (size_t)n * H_DIM + kk + c8;
            int so = n * AS + c8;
            *(uint4*)(Bgh + so) = *(const uint4*)(wgh + gi);
            *(uint4*)(Bgl + so) = *(const uint4*)(wgl + gi);
            *(uint4*)(Buh + so) = *(const uint4*)(wuh + gi);
            *(uint4*)(Bul + so) = *(const uint4*)(wul + gi);
        }
        __syncthreads();

#pragma unroll
        for (int ks = 0; ks < 4; ks++) {
            uint32_t ah[2][4], al[2][4];
#pragma unroll
            for (int mf = 0; mf < 2; mf++) {
                int so = (wm*32 + mf*16 + lr) * AS + ks*16 + lc;
                ldsm_x4(ah[mf], smem_u32(Ah + so));
                ldsm_x4(al[mf], smem_u32(Al + so));
            }
            uint32_t bgh[2][4], bgl[2][4], buh[2][4], bul[2][4];
#pragma unroll
            for (int n2 = 0; n2 < 2; n2++) {
                int so = (wn*32 + n2*16 + lr) * AS + ks*16 + lc;
                ldsm_x4(bgh[n2], smem_u32(Bgh + so));
                ldsm_x4(bgl[n2], smem_u32(Bgl + so));
                ldsm_x4(buh[n2], smem_u32(Buh + so));
                ldsm_x4(bul[n2], smem_u32(Bul + so));
            }
#pragma unroll
            for (int mf = 0; mf < 2; mf++)
#pragma unroll
            for (int nf = 0; nf < 4; nf++) {
                int n2 = nf >> 1, nh = nf & 1;
                uint32_t bG [2] = { bgh[n2][nh], bgh[n2][nh+2] };
                uint32_t bGl[2] = { bgl[n2][nh], bgl[n2][nh+2] };
                mma_bf16(cg[mf][nf], ah[mf], bG);
                mma_bf16(cg[mf][nf], al[mf], bG);
                mma_bf16(cg[mf][nf], ah[mf], bGl);
                uint32_t bU [2] = { buh[n2][nh], buh[n2][nh+2] };
                uint32_t bUl[2] = { bul[n2][nh], bul[n2][nh+2] };
                mma_bf16(cu[mf][nf], ah[mf], bU);
                mma_bf16(cu[mf][nf], al[mf], bU);
                mma_bf16(cu[mf][nf], ah[mf], bUl);
            }
        }
    }

    // epilogue: h = silu(g) * u, split-bf16 packed stores
    const int off = g_off[e];
#pragma unroll
    for (int mf = 0; mf < 2; mf++)
#pragma unroll
    for (int nf = 0; nf < 4; nf++) {
        int col = nt*64 + wn*32 + nf*8 + (lane & 3)*2;
#pragma unroll
        for (int half = 0; half < 2; half++) {
            int row = mt*128 + wm*32 + mf*16 + (lane >> 2) + half*8;
            if (row < cnt) {
                float g0 = cg[mf][nf][half*2],   g1 = cg[mf][nf][half*2+1];
                float u0 = cu[mf][nf][half*2],   u1 = cu[mf][nf][half*2+1];
                float h0 = (g0 / (1.f + expf(-g0))) * u0;
                float h1 = (g1 / (1.f + expf(-g1))) * u1;
                __nv_bfloat16 a0,b0,a1,b1;
                split_bf16(h0, a0, b0); split_bf16(h1, a1, b1);
                size_t base = (size_t)(off + row) * I_DIM + col;
                *(uint32_t*)(g_h_hi + base) = pack2(a0, a1);
                *(uint32_t*)(g_h_lo + base) = pack2(b0, b1);
            }
        }
    }
}

// ---------------------------------------------------------------------------
__global__ __launch_bounds__(256) void gemm2_kernel()
{
    const int e  = blockIdx.z;
    const int mt = blockIdx.y;
    const int nt = blockIdx.x;
    const int cnt = g_cnt[e];
    if (mt * 128 >= cnt) return;
    const int tid = threadIdx.x;
    const int wid = tid >> 5;
    const int lane = tid & 31;
    const int off = g_off[e];

    extern __shared__ __nv_bfloat16 sm[];
    __nv_bfloat16* Ah = sm;
    __nv_bfloat16* Al = sm + 128*AS;
    __nv_bfloat16* Bh = sm + 2*128*AS;
    __nv_bfloat16* Bl = Bh + 64*AS;

    const size_t wbase = (size_t)e * H_DIM * I_DIM + (size_t)(nt * 64) * I_DIM;
    const __nv_bfloat16* wdh = g_wd_hi + wbase;
    const __nv_bfloat16* wdl = g_wd_lo + wbase;

    float cc[2][4][4];
#pragma unroll
    for (int i = 0; i < 2; i++)
#pragma unroll
        for (int j = 0; j < 4; j++)
#pragma unroll
            for (int k = 0; k < 4; k++) cc[i][j][k] = 0.f;

    const int wm = wid >> 1;
    const int wn = wid & 1;
    const int lr = lane & 15;
    const int lc = (lane >> 4) * 8;

    for (int kk = 0; kk < I_DIM; kk += 64) {
        __syncthreads();
#pragma unroll
        for (int p = 0; p < 4; p++) {
            int q = tid + p * 256;
            int r = q >> 3, c8 = (q & 7) * 8;
            size_t gi = (size_t)(off + mt*128 + r) * I_DIM + kk + c8;
            uint4 vh = *(const uint4*)(g_h_hi + gi);
            uint4 vl = *(const uint4*)(g_h_lo + gi);
            int so = r * AS + c8;
            *(uint4*)(Ah + so) = vh;
            *(uint4*)(Al + so) = vl;
        }
#pragma unroll
        for (int p = 0; p < 2; p++) {
            int q = tid + p * 256;
            int n = q >> 3, c8 = (q & 7) * 8;
            size_t gi = (size_t)n * I_DIM + kk + c8;
            int so = n * AS + c8;
            *(uint4*)(Bh + so) = *(const uint4*)(wdh + gi);
            *(uint4*)(Bl + so) = *(const uint4*)(wdl + gi);
        }
        __syncthreads();

#pragma unroll
        for (int ks = 0; ks < 4; ks++) {
            uint32_t ah[2][4], al[2][4];
#pragma unroll
            for (int mf = 0; mf < 2; mf++) {
                int so = (wm*32 + mf*16 + lr) * AS + ks*16 + lc;
                ldsm_x4(ah[mf], smem_u32(Ah + so));
                ldsm_x4(al[mf], smem_u32(Al + so));
            }
            uint32_t bh[2][4], bl[2][4];
#pragma unroll
            for (int n2 = 0; n2 < 2; n2++) {
                int so = (wn*32 + n2*16 + lr) * AS + ks*16 + lc;
                ldsm_x4(bh[n2], smem_u32(Bh + so));
                ldsm_x4(bl[n2], smem_u32(Bl + so));
            }
#pragma unroll
            for (int mf = 0; mf < 2; mf++)
#pragma unroll
            for (int nf = 0; nf < 4; nf++) {
                int n2 = nf >> 1, nh = nf & 1;
                uint32_t bH[2] = { bh[n2][nh], bh[n2][nh+2] };
                uint32_t bL[2] = { bl[n2][nh], bl[n2][nh+2] };
                mma_bf16(cc[mf][nf], ah[mf], bH);
                mma_bf16(cc[mf][nf], al[mf], bH);
                mma_bf16(cc[mf][nf], ah[mf], bL);
            }
        }
    }

    // epilogue: store unscaled y rows (fp32)
#pragma unroll
    for (int mf = 0; mf < 2; mf++)
#pragma unroll
    for (int nf = 0; nf < 4; nf++) {
        int col = nt*64 + wn*32 + nf*8 + (lane & 3)*2;
#pragma unroll
        for (int half = 0; half < 2; half++) {
            int row = mt*128 + wm*32 + mf*16 + (lane >> 2) + half*8;
            if (row < cnt) {
                float2 v = make_float2(cc[mf][nf][half*2], cc[mf][nf][half*2+1]);
                *(float2*)(g_y + (size_t)(off + row) * H_DIM + col) = v;
            }
        }
    }
}

// ---------------------------------------------------------------------------
__global__ __launch_bounds__(256) void combine_kernel(float* __restrict__ out)
{
    const int t = blockIdx.x;
    const int tid = threadIdx.x;
    const int e0 = g_te[2*t],   p0 = g_tp[2*t];
    const int e1 = g_te[2*t+1], p1 = g_tp[2*t+1];
    const float w0 = g_tw[2*t], w1 = g_tw[2*t+1];
    const float* y0 = g_y + (size_t)(g_off[e0] + p0) * H_DIM;
    const float* y1 = g_y + (size_t)(g_off[e1] + p1) * H_DIM;
    float* o = out + (size_t)t * H_DIM;
#pragma unroll
    for (int it = 0; it < 2; it++) {
        int i = (tid + it * 256) * 4;
        float4 a = *(const float4*)(y0 + i);
        float4 b = *(const float4*)(y1 + i);
        float4 r;
        r.x = w0 * a.x + w1 * b.x;
        r.y = w0 * a.y + w1 * b.y;
        r.z = w0 * a.z + w1 * b.z;
        r.w = w0 * a.w + w1 * b.w;
        *(float4*)(o + i) = r;
    }
}

// ---------------------------------------------------------------------------
extern "C" void kernel_launch(void* const* d_in, const int* in_sizes, int n_in,
                              void* d_out, int out_size)
{
    const float* hs   = (const float*)d_in[0];
    const float* rmsw = (const float*)d_in[1];
    const float* rw   = (const float*)d_in[2];
    const float* wg   = (const float*)d_in[3];
    const float* wu   = (const float*)d_in[4];
    const float* wd   = (const float*)d_in[5];

    float* out        = (float*)d_out;
    float* out_logits = (float*)d_out + (size_t)T_TOKENS * H_DIM;

    cudaFuncSetAttribute(gemm1_kernel, cudaFuncAttributeMaxDynamicSharedMemorySize, G1_SMEM);
    cudaFuncSetAttribute(gemm2_kernel, cudaFuncAttributeMaxDynamicSharedMemorySize, G2_SMEM);

    // pre-split weights (once per launch; graph-capturable)
    {
        __nv_bfloat16 *wgh, *wgl, *wuh, *wul, *wdh, *wdl;
        cudaGetSymbolAddress((void**)&wgh, g_wg_hi);
        cudaGetSymbolAddress((void**)&wgl, g_wg_lo);
        cudaGetSymbolAddress((void**)&wuh, g_wu_hi);
        cudaGetSymbolAddress((void**)&wul, g_wu_lo);
        cudaGetSymbolAddress((void**)&wdh, g_wd_hi);
        cudaGetSymbolAddress((void**)&wdl, g_wd_lo);
        int n4 = WELEMS / 4;
        int blocks = (n4 + 255) / 256;
        split_kernel<<<blocks, 256>>>(wg, wgh, wgl, n4);
        split_kernel<<<blocks, 256>>>(wu, wuh, wul, n4);
        split_kernel<<<blocks, 256>>>(wd, wdh, wdl, n4);
    }

    reset_kernel<<<1, 32>>>();
    router_kernel<<<T_TOKENS, 256>>>(hs, rmsw, rw, out_logits);
    offsets_kernel<<<1, 1>>>();

    dim3 g1(I_DIM / 64, T_TOKENS / 128, N_EXP);   // 22 x 64 x 8
    gemm1_kernel<<<g1, 256, G1_SMEM>>>();

    dim3 g2(H_DIM / 64, T_TOKENS / 128, N_EXP);   // 32 x 64 x 8
    gemm2_kernel<<<g2, 256, G2_SMEM>>>();

    combine_kernel<<<T_TOKENS, 256>>>(out);
}